// round 12
// baseline (speedup 1.0000x reference)
#include <cuda_runtime.h>
#include <cuda_fp16.h>
#include <mma.h>
using namespace nvcuda;

#define MAX_NODES 50000
#define PAD_NODES 50176   // multiple of 128 (wmma tile safety)
#define CSR_STRIDE 96
#define D 128
#define D4 (D / 4)

// GEMM smem geometry (padded rows: 136 halves = 272B, conflict-friendly)
// Epilogue band ALIASES Ash (per-warp identical byte ranges) -> 69632 B total
// -> 3 CTAs/SM instead of 2.
#define APAD 136
#define SPAD 68
#define GEMM_DYN_SMEM (2 * 128 * APAD * 2)   // Ash + Wsh = 69632 B

// Scratch (device globals — no allocation allowed in kernel_launch)
__device__ __align__(256) __half g_hs[PAD_NODES * D];    // fp16 messages (ns applied)
__device__ __align__(256) __half g_aggh[PAD_NODES * D];  // fp16 agg result (*nd applied)
__device__ __align__(256) __half g_w16[2][D * D];        // fp16 weights
__device__ float g_ns[MAX_NODES];                        // rsqrt(out_deg)
__device__ int   g_degs[MAX_NODES];                      // REAL out-degree (init 0)
__device__ int   g_cnt[MAX_NODES];                       // real in-degree / fill cursor
__device__ __align__(16) int g_csr[MAX_NODES * CSR_STRIDE]; // fixed-stride CSR (by dst)

// ---------------------------------------------------------------------------
// K1: one pass over edges — out-degree count + CSR fill (cursor = in-degree).
__global__ void edgefill_kernel(const int4* __restrict__ src4,
                                const int4* __restrict__ dst4, int e4, int e) {
    int i = blockIdx.x * blockDim.x + threadIdx.x;
    if (i >= e4) return;
    int4 s = __ldg(src4 + i);
    int4 d = __ldg(dst4 + i);
    int rem = e - i * 4;   // >=4 except possibly the last thread
#define EF_ONE(SS, DD, K)                                              \
    if (K < rem) {                                                     \
        atomicAdd(&g_degs[SS], 1);                                     \
        int pos = atomicAdd(&g_cnt[DD], 1);                            \
        if (pos < CSR_STRIDE) g_csr[(DD) * CSR_STRIDE + pos] = (SS);   \
    }
    EF_ONE(s.x, d.x, 0)
    EF_ONE(s.y, d.y, 1)
    EF_ONE(s.z, d.z, 2)
    EF_ONE(s.w, d.w, 3)
#undef EF_ONE
}

// K2: node part: ns + hs = half(feat*ns). Tail blocks: W1/W2 -> fp16.
__global__ void prep_kernel(const float4* __restrict__ feat,
                            const float* __restrict__ W1,
                            const float* __restrict__ W2,
                            int n, int node_blocks) {
    if ((int)blockIdx.x >= node_blocks) {
        int i = (blockIdx.x - node_blocks) * 256 + threadIdx.x;  // 0..32767
        if (i < D * D)           g_w16[0][i]         = __float2half_rn(W1[i]);
        else if (i < 2 * D * D)  g_w16[1][i - D * D] = __float2half_rn(W2[i - D * D]);
        return;
    }
    int t = blockIdx.x * blockDim.x + threadIdx.x;
    int node = t >> 5;
    int part = t & 31;
    if (node >= n) return;
    float ns = rsqrtf((float)(g_degs[node] + 1));   // +1 = self loop
    if (part == 0) g_ns[node] = ns;
    float4 v = feat[node * D4 + part];
    __half2 h0 = __floats2half2_rn(v.x * ns, v.y * ns);
    __half2 h1 = __floats2half2_rn(v.z * ns, v.w * ns);
    uint2 u;
    u.x = *(unsigned*)&h0;
    u.y = *(unsigned*)&h1;
    ((uint2*)g_hs)[node * 32 + part] = u;
}

// ---------------------------------------------------------------------------
// K3/K5: CSR gather aggregation — AT its L2-traffic floor (12.3 TB/s). Frozen.
#define ACC8(A, U) do {                                                 \
        float2 _f;                                                      \
        _f = __half22float2(*(__half2*)&(U).x); A[0] += _f.x; A[1] += _f.y; \
        _f = __half22float2(*(__half2*)&(U).y); A[2] += _f.x; A[3] += _f.y; \
        _f = __half22float2(*(__half2*)&(U).z); A[4] += _f.x; A[5] += _f.y; \
        _f = __half22float2(*(__half2*)&(U).w); A[6] += _f.x; A[7] += _f.y; \
    } while (0)

#define HADD2V4(R, X, Y) do {                                               \
        *(__half2*)&(R).x = __hadd2(*(__half2*)&(X).x, *(__half2*)&(Y).x);  \
        *(__half2*)&(R).y = __hadd2(*(__half2*)&(X).y, *(__half2*)&(Y).y);  \
        *(__half2*)&(R).z = __hadd2(*(__half2*)&(X).z, *(__half2*)&(Y).z);  \
        *(__half2*)&(R).w = __hadd2(*(__half2*)&(X).w, *(__half2*)&(Y).w);  \
    } while (0)

#define TREE4(A, E0, E1, E2, E3) do {                                   \
        uint4 _u0 = __ldg(hsv + (E0) * 16 + hl);                        \
        uint4 _u1 = __ldg(hsv + (E1) * 16 + hl);                        \
        uint4 _u2 = __ldg(hsv + (E2) * 16 + hl);                        \
        uint4 _u3 = __ldg(hsv + (E3) * 16 + hl);                        \
        uint4 _s01, _s23, _s;                                           \
        HADD2V4(_s01, _u0, _u1);                                        \
        HADD2V4(_s23, _u2, _u3);                                        \
        HADD2V4(_s, _s01, _s23);                                        \
        ACC8(A, _s);                                                    \
    } while (0)

__global__ void __launch_bounds__(256) aggregate_kernel(int n) {
    int gw   = (blockIdx.x * blockDim.x + threadIdx.x) >> 5;
    int lane = threadIdx.x & 31;
    int half = lane >> 4;       // which node of the pair
    int hl   = lane & 15;       // lane within half: 16 x uint4 = 256B row
    int node = gw * 2 + half;
    if (gw * 2 >= n) return;
    if (node >= n) node = n - 1;   // duplicate compute, identical bytes written

    const uint4* hsv = (const uint4*)g_hs;

    float a[8];
    {   // self-loop seed
        uint4 s = __ldg(hsv + node * 16 + hl);
        a[0] = a[1] = a[2] = a[3] = a[4] = a[5] = a[6] = a[7] = 0.f;
        ACC8(a, s);
    }

    int cnt = g_cnt[node];                       // true in-degree
    int ce  = cnt < CSR_STRIDE ? cnt : CSR_STRIDE;
    const int* row = g_csr + node * CSR_STRIDE;

    int base = 0;
    for (; base + 8 <= ce; base += 8) {          // 8-edge unroll: 2 idx LDG.128
        int4 e0 = __ldg((const int4*)(row + base));
        int4 e1 = __ldg((const int4*)(row + base + 4));
        TREE4(a, e0.x, e0.y, e0.z, e0.w);
        TREE4(a, e1.x, e1.y, e1.z, e1.w);
    }
    if (base + 4 <= ce) {
        int4 e0 = __ldg((const int4*)(row + base));
        TREE4(a, e0.x, e0.y, e0.z, e0.w);
        base += 4;
    }
    for (; base < ce; base++) {                  // exact fp32 tail
        int ei = __ldg(row + base);
        uint4 u = __ldg(hsv + ei * 16 + hl);
        ACC8(a, u);
    }

    float nd = rsqrtf((float)(cnt + 1));
    __half2 h0 = __floats2half2_rn(a[0] * nd, a[1] * nd);
    __half2 h1 = __floats2half2_rn(a[2] * nd, a[3] * nd);
    __half2 h2 = __floats2half2_rn(a[4] * nd, a[5] * nd);
    __half2 h3 = __floats2half2_rn(a[6] * nd, a[7] * nd);
    uint4 o;
    o.x = *(unsigned*)&h0; o.y = *(unsigned*)&h1;
    o.z = *(unsigned*)&h2; o.w = *(unsigned*)&h3;
    ((uint4*)g_aggh)[node * 16 + hl] = o;
}

// ---------------------------------------------------------------------------
// K4/K6: HMMA GEMM — R8 structure, but the epilogue band ALIASES Ash:
// warp w's band bytes [w*4352, (w+1)*4352) == its own Ash rows, which it has
// fully consumed before the epilogue (program order within the warp).
// 69.6 KB smem -> 3 CTAs/SM, 391 blocks in ONE wave.
__global__ void __launch_bounds__(256, 3)
gemm_wmma_kernel(int layer, const float* __restrict__ bias,
                 float* __restrict__ out, int n, int mode) {
    extern __shared__ unsigned char dyn[];
    __half* Ash  = (__half*)dyn;                    // 128 x APAD
    __half* Wsh  = Ash + 128 * APAD;                // 128 x APAD
    float*  stg  = (float*)dyn;                     // band aliases Ash

    int tid = threadIdx.x;
    int warp = tid >> 5;
    int lane = tid & 31;
    int row0 = blockIdx.x * 128;

    // Cooperative coalesced staging: A tile and W.
    const uint4* Ag = (const uint4*)(g_aggh + (size_t)row0 * D);  // 16 uint4/row
    const uint4* Wg = (const uint4*)g_w16[layer];
#pragma unroll
    for (int s = 0; s < 8; s++) {
        int i = tid + 256 * s;          // 0..2047
        int r = i >> 4, c = i & 15;
        ((uint4*)Ash)[r * (APAD / 8) + c] = Ag[i];
        ((uint4*)Wsh)[r * (APAD / 8) + c] = Wg[i];
    }
    __syncthreads();

    wmma::fragment<wmma::accumulator, 16, 16, 16, float> acc[8];
#pragma unroll
    for (int j = 0; j < 8; j++) wmma::fill_fragment(acc[j], 0.0f);

#pragma unroll
    for (int k = 0; k < 8; k++) {
        wmma::fragment<wmma::matrix_a, 16, 16, 16, __half, wmma::row_major> a;
        wmma::load_matrix_sync(a, Ash + (warp * 16) * APAD + k * 16, APAD);
#pragma unroll
        for (int j = 0; j < 8; j++) {
            wmma::fragment<wmma::matrix_b, 16, 16, 16, __half, wmma::row_major> b;
            wmma::load_matrix_sync(b, Wsh + (k * 16) * APAD + j * 16, APAD);
            wmma::mma_sync(acc[j], a, b, acc[j]);
        }
    }

    // Epilogue: 2 rounds x 4 tiles into a 16 x 64 per-warp fp32 band
    // (band = this warp's own, already-consumed Ash rows).
    float* band = stg + warp * 16 * SPAD;
    int er = lane >> 1;             // row in band
    int eh = lane & 1;              // which 32-col half
    int row = row0 + warp * 16 + er;
#pragma unroll
    for (int rnd = 0; rnd < 2; rnd++) {
#pragma unroll
        for (int j = 0; j < 4; j++)
            wmma::store_matrix_sync(band + j * 16, acc[rnd * 4 + j], SPAD,
                                    wmma::mem_row_major);
        __syncwarp();
        if (row < n) {
            int col = rnd * 64 + eh * 32;
            const float* srow = band + er * SPAD + eh * 32;
            float v[32];
#pragma unroll
            for (int q = 0; q < 8; q++) {
                float4 x = *(const float4*)(srow + q * 4);
                float4 bb = *(const float4*)(bias + col + q * 4);
                v[q * 4 + 0] = x.x + bb.x; v[q * 4 + 1] = x.y + bb.y;
                v[q * 4 + 2] = x.z + bb.z; v[q * 4 + 3] = x.w + bb.w;
            }
            if (mode == 1) {
                float s = g_ns[row];
#pragma unroll
                for (int c = 0; c < 32; c++) v[c] = fmaxf(v[c], 0.0f) * s;
#pragma unroll
                for (int q = 0; q < 4; q++) {
                    __half2 p0 = __floats2half2_rn(v[q * 8 + 0], v[q * 8 + 1]);
                    __half2 p1 = __floats2half2_rn(v[q * 8 + 2], v[q * 8 + 3]);
                    __half2 p2 = __floats2half2_rn(v[q * 8 + 4], v[q * 8 + 5]);
                    __half2 p3 = __floats2half2_rn(v[q * 8 + 6], v[q * 8 + 7]);
                    uint4 u;
                    u.x = *(unsigned*)&p0; u.y = *(unsigned*)&p1;
                    u.z = *(unsigned*)&p2; u.w = *(unsigned*)&p3;
                    *(uint4*)(g_hs + row * D + col + q * 8) = u;
                }
            } else {
#pragma unroll
                for (int q = 0; q < 8; q++)
                    *(float4*)(out + row * D + col + q * 4) =
                        make_float4(v[q * 4], v[q * 4 + 1],
                                    v[q * 4 + 2], v[q * 4 + 3]);
            }
        }
        __syncwarp();
    }
}

// ---------------------------------------------------------------------------
extern "C" void kernel_launch(void* const* d_in, const int* in_sizes, int n_in,
                              void* d_out, int out_size) {
    const float* feat = (const float*)d_in[0];
    const float* W1   = (const float*)d_in[1];
    const float* b1   = (const float*)d_in[2];
    const float* W2   = (const float*)d_in[3];
    const float* b2   = (const float*)d_in[4];
    const int*   src  = (const int*)d_in[5];
    const int*   dst  = (const int*)d_in[6];
    float* out = (float*)d_out;

    int n_nodes = in_sizes[0] / D;
    int n_edges = in_sizes[5];
    if (n_nodes > MAX_NODES) n_nodes = MAX_NODES;

    cudaFuncSetAttribute(gemm_wmma_kernel,
                         cudaFuncAttributeMaxDynamicSharedMemorySize,
                         GEMM_DYN_SMEM);

    // Zero degree/cursor arrays via async memset (graph-capturable, no kernel)
    void *degs_ptr = nullptr, *cnt_ptr = nullptr;
    cudaGetSymbolAddress(&degs_ptr, g_degs);
    cudaGetSymbolAddress(&cnt_ptr, g_cnt);
    cudaMemsetAsync(degs_ptr, 0, n_nodes * sizeof(int));
    cudaMemsetAsync(cnt_ptr, 0, n_nodes * sizeof(int));

    int node_blocks = (n_nodes * 32 + 255) / 256;
    int w_blocks = (2 * D * D + 255) / 256;          // 128
    int agg_blocks = ((n_nodes + 1) / 2 * 32 + 255) / 256;
    int gemm_blocks = (n_nodes + 127) / 128;
    int e4 = (n_edges + 3) / 4;

    // 1: degree+CSR in one pass; 2: prep (+W convert in tail blocks)
    edgefill_kernel<<<(e4 + 255) / 256, 256>>>((const int4*)src,
                                               (const int4*)dst, e4, n_edges);
    prep_kernel<<<node_blocks + w_blocks, 256>>>((const float4*)feat, W1, W2,
                                                 n_nodes, node_blocks);

    // Layer 1  (gemm is kernel #4 -> lands in the ncu capture slot)
    aggregate_kernel<<<agg_blocks, 256>>>(n_nodes);
    gemm_wmma_kernel<<<gemm_blocks, 256, GEMM_DYN_SMEM>>>(0, b1, nullptr,
                                                          n_nodes, 1);

    // Layer 2
    aggregate_kernel<<<agg_blocks, 256>>>(n_nodes);
    gemm_wmma_kernel<<<gemm_blocks, 256, GEMM_DYN_SMEM>>>(1, b2, out,
                                                          n_nodes, 0);
}

// round 14
// speedup vs baseline: 1.0137x; 1.0137x over previous
#include <cuda_runtime.h>
#include <cuda_fp16.h>
#include <mma.h>
using namespace nvcuda;

#define MAX_NODES 50000
#define PAD_NODES 50176   // multiple of 128 (wmma tile safety)
#define CSR_STRIDE 96
#define D 128
#define D4 (D / 4)

// GEMM smem geometry (padded rows: 136 halves = 272B, conflict-friendly)
#define APAD 136
#define SPAD 68
#define GEMM_DYN_SMEM (2 * 128 * APAD * 2 + 8 * 16 * SPAD * 4)  // 104448 B

// Scratch (device globals — no allocation allowed in kernel_launch)
__device__ __align__(256) __half g_hs[PAD_NODES * D];    // fp16 messages (ns applied)
__device__ __align__(256) __half g_aggh[PAD_NODES * D];  // fp16 agg result (*nd applied)
__device__ __align__(256) __half g_w16[2][D * D];        // fp16 weights
__device__ float g_ns[MAX_NODES];                        // rsqrt(out_deg)
__device__ int   g_degs[MAX_NODES];                      // out-degree (init 1)
__device__ int   g_cnt[MAX_NODES];                       // real in-degree / fill cursor
__device__ __align__(16) int g_csr[MAX_NODES * CSR_STRIDE]; // fixed-stride CSR (by dst)

// ---------------------------------------------------------------------------
// K1: init degs=1 (self-loop), cursor=0. Must run every launch.
__global__ void init_kernel(int n) {
    int i = blockIdx.x * blockDim.x + threadIdx.x;
    if (i < n) { g_degs[i] = 1; g_cnt[i] = 0; }
}

// K2: one pass over edges — out-degree count + CSR fill (cursor = in-degree)
__global__ void edgefill_kernel(const int* __restrict__ src,
                                const int* __restrict__ dst, int e) {
    int i = blockIdx.x * blockDim.x + threadIdx.x;
    if (i < e) {
        int s = __ldg(src + i);
        int d = __ldg(dst + i);
        atomicAdd(&g_degs[s], 1);
        int pos = atomicAdd(&g_cnt[d], 1);
        if (pos < CSR_STRIDE) g_csr[d * CSR_STRIDE + pos] = s;
    }
}

// K3: node part: ns + hs = half(feat*ns). Tail blocks: W1/W2 -> fp16.
__global__ void prep_kernel(const float4* __restrict__ feat,
                            const float* __restrict__ W1,
                            const float* __restrict__ W2,
                            int n, int node_blocks) {
    if ((int)blockIdx.x >= node_blocks) {
        int i = (blockIdx.x - node_blocks) * 256 + threadIdx.x;  // 0..32767
        if (i < D * D)           g_w16[0][i]         = __float2half_rn(W1[i]);
        else if (i < 2 * D * D)  g_w16[1][i - D * D] = __float2half_rn(W2[i - D * D]);
        return;
    }
    int t = blockIdx.x * blockDim.x + threadIdx.x;
    int node = t >> 5;
    int part = t & 31;
    if (node >= n) return;
    float ns = rsqrtf((float)g_degs[node]);
    if (part == 0) g_ns[node] = ns;
    float4 v = feat[node * D4 + part];
    __half2 h0 = __floats2half2_rn(v.x * ns, v.y * ns);
    __half2 h1 = __floats2half2_rn(v.z * ns, v.w * ns);
    uint2 u;
    u.x = *(unsigned*)&h0;
    u.y = *(unsigned*)&h1;
    ((uint2*)g_hs)[node * 32 + part] = u;
}

// ---------------------------------------------------------------------------
// K4/K6: CSR gather aggregation — TWO nodes per warp (16 lanes each, uint4
// loads). Groups of 8 edges pre-summed in fp16 (3-level HADD2 tree), one fp32
// fold per group: 52 issue slots per 8 edges vs 64 for the 4-tree.
#define ACC8(A, U) do {                                                 \
        float2 _f;                                                      \
        _f = __half22float2(*(__half2*)&(U).x); A[0] += _f.x; A[1] += _f.y; \
        _f = __half22float2(*(__half2*)&(U).y); A[2] += _f.x; A[3] += _f.y; \
        _f = __half22float2(*(__half2*)&(U).z); A[4] += _f.x; A[5] += _f.y; \
        _f = __half22float2(*(__half2*)&(U).w); A[6] += _f.x; A[7] += _f.y; \
    } while (0)

#define HADD2V4(R, X, Y) do {                                               \
        *(__half2*)&(R).x = __hadd2(*(__half2*)&(X).x, *(__half2*)&(Y).x);  \
        *(__half2*)&(R).y = __hadd2(*(__half2*)&(X).y, *(__half2*)&(Y).y);  \
        *(__half2*)&(R).z = __hadd2(*(__half2*)&(X).z, *(__half2*)&(Y).z);  \
        *(__half2*)&(R).w = __hadd2(*(__half2*)&(X).w, *(__half2*)&(Y).w);  \
    } while (0)

#define TREE4(A, E0, E1, E2, E3) do {                                   \
        uint4 _u0 = __ldg(hsv + (E0) * 16 + hl);                        \
        uint4 _u1 = __ldg(hsv + (E1) * 16 + hl);                        \
        uint4 _u2 = __ldg(hsv + (E2) * 16 + hl);                        \
        uint4 _u3 = __ldg(hsv + (E3) * 16 + hl);                        \
        uint4 _s01, _s23, _s;                                           \
        HADD2V4(_s01, _u0, _u1);                                        \
        HADD2V4(_s23, _u2, _u3);                                        \
        HADD2V4(_s, _s01, _s23);                                        \
        ACC8(A, _s);                                                    \
    } while (0)

// 8-edge group: all 8 loads issued back-to-back (MLP=8), 3-level fp16 tree,
// single fp32 fold.
#define TREE8(A, E) do {                                                \
        uint4 _u0 = __ldg(hsv + (E).x * 16 + hl);                       \
        uint4 _u1 = __ldg(hsv + (E).y * 16 + hl);                       \
        uint4 _u2 = __ldg(hsv + (E).z * 16 + hl);                       \
        uint4 _u3 = __ldg(hsv + (E).w * 16 + hl);                       \
        uint4 _u4 = __ldg(hsv + (E2).x * 16 + hl);                      \
        uint4 _u5 = __ldg(hsv + (E2).y * 16 + hl);                      \
        uint4 _u6 = __ldg(hsv + (E2).z * 16 + hl);                      \
        uint4 _u7 = __ldg(hsv + (E2).w * 16 + hl);                      \
        uint4 _a, _b, _c, _d, _ab, _cd, _s;                             \
        HADD2V4(_a, _u0, _u1);                                          \
        HADD2V4(_b, _u2, _u3);                                          \
        HADD2V4(_c, _u4, _u5);                                          \
        HADD2V4(_d, _u6, _u7);                                          \
        HADD2V4(_ab, _a, _b);                                           \
        HADD2V4(_cd, _c, _d);                                           \
        HADD2V4(_s, _ab, _cd);                                          \
        ACC8(A, _s);                                                    \
    } while (0)

__global__ void __launch_bounds__(256) aggregate_kernel(int n) {
    int gw   = (blockIdx.x * blockDim.x + threadIdx.x) >> 5;
    int lane = threadIdx.x & 31;
    int half = lane >> 4;       // which node of the pair
    int hl   = lane & 15;       // lane within half: 16 x uint4 = 256B row
    int node = gw * 2 + half;
    if (gw * 2 >= n) return;
    if (node >= n) node = n - 1;   // duplicate compute, identical bytes written

    const uint4* hsv = (const uint4*)g_hs;

    float a[8];
    {   // self-loop seed
        uint4 s = __ldg(hsv + node * 16 + hl);
        a[0] = a[1] = a[2] = a[3] = a[4] = a[5] = a[6] = a[7] = 0.f;
        ACC8(a, s);
    }

    int cnt = g_cnt[node];                       // true in-degree
    int ce  = cnt < CSR_STRIDE ? cnt : CSR_STRIDE;
    const int* row = g_csr + node * CSR_STRIDE;

    int base = 0;
    for (; base + 8 <= ce; base += 8) {          // 8-edge tree groups
        int4 E  = __ldg((const int4*)(row + base));
        int4 E2 = __ldg((const int4*)(row + base + 4));
        TREE8(a, E);
    }
    if (base + 4 <= ce) {
        int4 e0 = __ldg((const int4*)(row + base));
        TREE4(a, e0.x, e0.y, e0.z, e0.w);
        base += 4;
    }
    for (; base < ce; base++) {                  // exact fp32 tail
        int ei = __ldg(row + base);
        uint4 u = __ldg(hsv + ei * 16 + hl);
        ACC8(a, u);
    }

    float nd = rsqrtf((float)(cnt + 1));
    __half2 h0 = __floats2half2_rn(a[0] * nd, a[1] * nd);
    __half2 h1 = __floats2half2_rn(a[2] * nd, a[3] * nd);
    __half2 h2 = __floats2half2_rn(a[4] * nd, a[5] * nd);
    __half2 h3 = __floats2half2_rn(a[6] * nd, a[7] * nd);
    uint4 o;
    o.x = *(unsigned*)&h0; o.y = *(unsigned*)&h1;
    o.z = *(unsigned*)&h2; o.w = *(unsigned*)&h3;
    ((uint4*)g_aggh)[node * 16 + hl] = o;
}

// ---------------------------------------------------------------------------
// K5/K7: HMMA GEMM — R8's measured-best structure, unchanged.
__global__ void __launch_bounds__(256)
gemm_wmma_kernel(int layer, const float* __restrict__ bias,
                 float* __restrict__ out, int n, int mode) {
    extern __shared__ unsigned char dyn[];
    __half* Ash  = (__half*)dyn;                    // 128 x APAD
    __half* Wsh  = Ash + 128 * APAD;                // 128 x APAD
    float*  stg  = (float*)(Wsh + 128 * APAD);      // 8 warps x 16 x SPAD

    int tid = threadIdx.x;
    int warp = tid >> 5;
    int lane = tid & 31;
    int row0 = blockIdx.x * 128;

    const uint4* Ag = (const uint4*)(g_aggh + (size_t)row0 * D);  // 16 uint4/row
    const uint4* Wg = (const uint4*)g_w16[layer];
#pragma unroll
    for (int s = 0; s < 8; s++) {
        int i = tid + 256 * s;          // 0..2047
        int r = i >> 4, c = i & 15;
        ((uint4*)Ash)[r * (APAD / 8) + c] = Ag[i];
        ((uint4*)Wsh)[r * (APAD / 8) + c] = Wg[i];
    }
    __syncthreads();

    wmma::fragment<wmma::accumulator, 16, 16, 16, float> acc[8];
#pragma unroll
    for (int j = 0; j < 8; j++) wmma::fill_fragment(acc[j], 0.0f);

#pragma unroll
    for (int k = 0; k < 8; k++) {
        wmma::fragment<wmma::matrix_a, 16, 16, 16, __half, wmma::row_major> a;
        wmma::load_matrix_sync(a, Ash + (warp * 16) * APAD + k * 16, APAD);
#pragma unroll
        for (int j = 0; j < 8; j++) {
            wmma::fragment<wmma::matrix_b, 16, 16, 16, __half, wmma::row_major> b;
            wmma::load_matrix_sync(b, Wsh + (k * 16) * APAD + j * 16, APAD);
            wmma::mma_sync(acc[j], a, b, acc[j]);
        }
    }

    float* band = stg + warp * 16 * SPAD;
    int er = lane >> 1;             // row in band
    int eh = lane & 1;              // which 32-col half
    int row = row0 + warp * 16 + er;
#pragma unroll
    for (int rnd = 0; rnd < 2; rnd++) {
#pragma unroll
        for (int j = 0; j < 4; j++)
            wmma::store_matrix_sync(band + j * 16, acc[rnd * 4 + j], SPAD,
                                    wmma::mem_row_major);
        __syncwarp();
        if (row < n) {
            int col = rnd * 64 + eh * 32;
            const float* srow = band + er * SPAD + eh * 32;
            float v[32];
#pragma unroll
            for (int q = 0; q < 8; q++) {
                float4 x = *(const float4*)(srow + q * 4);
                float4 bb = *(const float4*)(bias + col + q * 4);
                v[q * 4 + 0] = x.x + bb.x; v[q * 4 + 1] = x.y + bb.y;
                v[q * 4 + 2] = x.z + bb.z; v[q * 4 + 3] = x.w + bb.w;
            }
            if (mode == 1) {
                float s = g_ns[row];
#pragma unroll
                for (int c = 0; c < 32; c++) v[c] = fmaxf(v[c], 0.0f) * s;
#pragma unroll
                for (int q = 0; q < 4; q++) {
                    __half2 p0 = __floats2half2_rn(v[q * 8 + 0], v[q * 8 + 1]);
                    __half2 p1 = __floats2half2_rn(v[q * 8 + 2], v[q * 8 + 3]);
                    __half2 p2 = __floats2half2_rn(v[q * 8 + 4], v[q * 8 + 5]);
                    __half2 p3 = __floats2half2_rn(v[q * 8 + 6], v[q * 8 + 7]);
                    uint4 u;
                    u.x = *(unsigned*)&p0; u.y = *(unsigned*)&p1;
                    u.z = *(unsigned*)&p2; u.w = *(unsigned*)&p3;
                    *(uint4*)(g_hs + row * D + col + q * 8) = u;
                }
            } else {
#pragma unroll
                for (int q = 0; q < 8; q++)
                    *(float4*)(out + row * D + col + q * 4) =
                        make_float4(v[q * 4], v[q * 4 + 1],
                                    v[q * 4 + 2], v[q * 4 + 3]);
            }
        }
        __syncwarp();
    }
}

// ---------------------------------------------------------------------------
extern "C" void kernel_launch(void* const* d_in, const int* in_sizes, int n_in,
                              void* d_out, int out_size) {
    const float* feat = (const float*)d_in[0];
    const float* W1   = (const float*)d_in[1];
    const float* b1   = (const float*)d_in[2];
    const float* W2   = (const float*)d_in[3];
    const float* b2   = (const float*)d_in[4];
    const int*   src  = (const int*)d_in[5];
    const int*   dst  = (const int*)d_in[6];
    float* out = (float*)d_out;

    int n_nodes = in_sizes[0] / D;
    int n_edges = in_sizes[5];
    if (n_nodes > MAX_NODES) n_nodes = MAX_NODES;

    cudaFuncSetAttribute(gemm_wmma_kernel,
                         cudaFuncAttributeMaxDynamicSharedMemorySize,
                         GEMM_DYN_SMEM);

    int node_blocks = (n_nodes * 32 + 255) / 256;
    int w_blocks = (2 * D * D + 255) / 256;          // 128
    int agg_blocks = ((n_nodes + 1) / 2 * 32 + 255) / 256;
    int gemm_blocks = (n_nodes + 127) / 128;

    // 1: init; 2: degree+CSR in one pass; 3: prep (+W convert in tail blocks)
    init_kernel<<<(n_nodes + 255) / 256, 256>>>(n_nodes);
    edgefill_kernel<<<(n_edges + 255) / 256, 256>>>(src, dst, n_edges);
    prep_kernel<<<node_blocks + w_blocks, 256>>>((const float4*)feat, W1, W2,
                                                 n_nodes, node_blocks);

    // Layer 1  (aggregate is kernel #4 -> lands in the ncu capture slot)
    aggregate_kernel<<<agg_blocks, 256>>>(n_nodes);
    gemm_wmma_kernel<<<gemm_blocks, 256, GEMM_DYN_SMEM>>>(0, b1, nullptr,
                                                          n_nodes, 1);

    // Layer 2
    aggregate_kernel<<<agg_blocks, 256>>>(n_nodes);
    gemm_wmma_kernel<<<gemm_blocks, 256, GEMM_DYN_SMEM>>>(1, b2, out,
                                                          n_nodes, 0);
}

// round 15
// speedup vs baseline: 1.0767x; 1.0621x over previous
#include <cuda_runtime.h>
#include <cuda_fp16.h>
#include <cstdint>

#define MAX_NODES 50000
#define PAD_NODES 50176   // multiple of 128 (tile safety)
#define CSR_STRIDE 96
#define D 128
#define D4 (D / 4)

#define APAD 136                       // padded row: 272B (68 words ≡ 4 mod 32)
#define GEMM_DYN_SMEM (2 * 128 * APAD * 2)   // Ash + Wsh = 69632 B, no band

// Scratch (device globals — no allocation allowed in kernel_launch)
__device__ __align__(256) __half g_hs[PAD_NODES * D];    // fp16 messages (ns applied)
__device__ __align__(256) __half g_aggh[PAD_NODES * D];  // fp16 agg result (*nd applied)
__device__ __align__(256) __half g_w16[2][D * D];        // fp16 weights [k][n]
__device__ float g_ns[MAX_NODES];                        // rsqrt(out_deg)
__device__ int   g_degs[MAX_NODES];                      // REAL out-degree (init 0)
__device__ int   g_cnt[MAX_NODES];                       // real in-degree / fill cursor
__device__ __align__(16) int g_csr[MAX_NODES * CSR_STRIDE]; // fixed-stride CSR (by dst)

static __device__ __forceinline__ uint32_t smem_u32(const void* p) {
    uint32_t a;
    asm("{ .reg .u64 t; cvta.to.shared.u64 t, %1; cvt.u32.u64 %0, t; }"
        : "=r"(a) : "l"(p));
    return a;
}

// ---------------------------------------------------------------------------
// K1: one pass over edges — out-degree count + CSR fill (cursor = in-degree).
__global__ void edgefill_kernel(const int4* __restrict__ src4,
                                const int4* __restrict__ dst4, int e4, int e) {
    int i = blockIdx.x * blockDim.x + threadIdx.x;
    if (i >= e4) return;
    int4 s = __ldg(src4 + i);
    int4 d = __ldg(dst4 + i);
    int rem = e - i * 4;
#define EF_ONE(SS, DD, K)                                              \
    if (K < rem) {                                                     \
        atomicAdd(&g_degs[SS], 1);                                     \
        int pos = atomicAdd(&g_cnt[DD], 1);                            \
        if (pos < CSR_STRIDE) g_csr[(DD) * CSR_STRIDE + pos] = (SS);   \
    }
    EF_ONE(s.x, d.x, 0)
    EF_ONE(s.y, d.y, 1)
    EF_ONE(s.z, d.z, 2)
    EF_ONE(s.w, d.w, 3)
#undef EF_ONE
}

// K2: node part: ns + hs = half(feat*ns). Tail blocks: W1/W2 -> fp16.
__global__ void prep_kernel(const float4* __restrict__ feat,
                            const float* __restrict__ W1,
                            const float* __restrict__ W2,
                            int n, int node_blocks) {
    if ((int)blockIdx.x >= node_blocks) {
        int i = (blockIdx.x - node_blocks) * 256 + threadIdx.x;  // 0..32767
        if (i < D * D)           g_w16[0][i]         = __float2half_rn(W1[i]);
        else if (i < 2 * D * D)  g_w16[1][i - D * D] = __float2half_rn(W2[i - D * D]);
        return;
    }
    int t = blockIdx.x * blockDim.x + threadIdx.x;
    int node = t >> 5;
    int part = t & 31;
    if (node >= n) return;
    float ns = rsqrtf((float)(g_degs[node] + 1));   // +1 = self loop
    if (part == 0) g_ns[node] = ns;
    float4 v = feat[node * D4 + part];
    __half2 h0 = __floats2half2_rn(v.x * ns, v.y * ns);
    __half2 h1 = __floats2half2_rn(v.z * ns, v.w * ns);
    uint2 u;
    u.x = *(unsigned*)&h0;
    u.y = *(unsigned*)&h1;
    ((uint2*)g_hs)[node * 32 + part] = u;
}

// ---------------------------------------------------------------------------
// K3/K5: CSR gather aggregation — R8's TREE4 form (regs 32, occ 94%); at its
// L2-traffic floor. Frozen.
#define ACC8(A, U) do {                                                 \
        float2 _f;                                                      \
        _f = __half22float2(*(__half2*)&(U).x); A[0] += _f.x; A[1] += _f.y; \
        _f = __half22float2(*(__half2*)&(U).y); A[2] += _f.x; A[3] += _f.y; \
        _f = __half22float2(*(__half2*)&(U).z); A[4] += _f.x; A[5] += _f.y; \
        _f = __half22float2(*(__half2*)&(U).w); A[6] += _f.x; A[7] += _f.y; \
    } while (0)

#define HADD2V4(R, X, Y) do {                                               \
        *(__half2*)&(R).x = __hadd2(*(__half2*)&(X).x, *(__half2*)&(Y).x);  \
        *(__half2*)&(R).y = __hadd2(*(__half2*)&(X).y, *(__half2*)&(Y).y);  \
        *(__half2*)&(R).z = __hadd2(*(__half2*)&(X).z, *(__half2*)&(Y).z);  \
        *(__half2*)&(R).w = __hadd2(*(__half2*)&(X).w, *(__half2*)&(Y).w);  \
    } while (0)

#define TREE4(A, E0, E1, E2, E3) do {                                   \
        uint4 _u0 = __ldg(hsv + (E0) * 16 + hl);                        \
        uint4 _u1 = __ldg(hsv + (E1) * 16 + hl);                        \
        uint4 _u2 = __ldg(hsv + (E2) * 16 + hl);                        \
        uint4 _u3 = __ldg(hsv + (E3) * 16 + hl);                        \
        uint4 _s01, _s23, _s;                                           \
        HADD2V4(_s01, _u0, _u1);                                        \
        HADD2V4(_s23, _u2, _u3);                                        \
        HADD2V4(_s, _s01, _s23);                                        \
        ACC8(A, _s);                                                    \
    } while (0)

__global__ void __launch_bounds__(256) aggregate_kernel(int n) {
    int gw   = (blockIdx.x * blockDim.x + threadIdx.x) >> 5;
    int lane = threadIdx.x & 31;
    int half = lane >> 4;
    int hl   = lane & 15;
    int node = gw * 2 + half;
    if (gw * 2 >= n) return;
    if (node >= n) node = n - 1;

    const uint4* hsv = (const uint4*)g_hs;

    float a[8];
    {   // self-loop seed
        uint4 s = __ldg(hsv + node * 16 + hl);
        a[0] = a[1] = a[2] = a[3] = a[4] = a[5] = a[6] = a[7] = 0.f;
        ACC8(a, s);
    }

    int cnt = g_cnt[node];
    int ce  = cnt < CSR_STRIDE ? cnt : CSR_STRIDE;
    const int* row = g_csr + node * CSR_STRIDE;

    int base = 0;
    for (; base + 8 <= ce; base += 8) {
        int4 e0 = __ldg((const int4*)(row + base));
        int4 e1 = __ldg((const int4*)(row + base + 4));
        TREE4(a, e0.x, e0.y, e0.z, e0.w);
        TREE4(a, e1.x, e1.y, e1.z, e1.w);
    }
    if (base + 4 <= ce) {
        int4 e0 = __ldg((const int4*)(row + base));
        TREE4(a, e0.x, e0.y, e0.z, e0.w);
        base += 4;
    }
    for (; base < ce; base++) {
        int ei = __ldg(row + base);
        uint4 u = __ldg(hsv + ei * 16 + hl);
        ACC8(a, u);
    }

    float nd = rsqrtf((float)(cnt + 1));
    __half2 h0 = __floats2half2_rn(a[0] * nd, a[1] * nd);
    __half2 h1 = __floats2half2_rn(a[2] * nd, a[3] * nd);
    __half2 h2 = __floats2half2_rn(a[4] * nd, a[5] * nd);
    __half2 h3 = __floats2half2_rn(a[6] * nd, a[7] * nd);
    uint4 o;
    o.x = *(unsigned*)&h0; o.y = *(unsigned*)&h1;
    o.z = *(unsigned*)&h2; o.w = *(unsigned*)&h3;
    ((uint4*)g_aggh)[node * 16 + hl] = o;
}

// ---------------------------------------------------------------------------
// K4/K6: explicit mma.sync GEMM. Warp = 16 rows x 128 cols = 16 m16n8k16
// tiles, acc in registers with KNOWN layout -> bias/relu/ns/pack applied in
// registers, stores straight to global. No epilogue smem band.
__global__ void __launch_bounds__(256)
gemm_mma_kernel(int layer, const float* __restrict__ bias,
                float* __restrict__ out, int n, int mode) {
    extern __shared__ unsigned char dyn[];
    __half* Ash = (__half*)dyn;                 // 128 x APAD
    __half* Wsh = Ash + 128 * APAD;             // 128 x APAD

    int tid = threadIdx.x, warp = tid >> 5, lane = tid & 31;
    int row0 = blockIdx.x * 128;

    // Cooperative coalesced staging (A rows < PAD_NODES always).
    const uint4* Ag = (const uint4*)(g_aggh + (size_t)row0 * D);
    const uint4* Wg = (const uint4*)g_w16[layer];
#pragma unroll
    for (int s = 0; s < 8; s++) {
        int i = tid + 256 * s;
        int r = i >> 4, c = i & 15;
        ((uint4*)Ash)[r * (APAD / 8) + c] = Ag[i];
        ((uint4*)Wsh)[r * (APAD / 8) + c] = Wg[i];
    }
    __syncthreads();

    float acc[16][4];
#pragma unroll
    for (int j = 0; j < 16; j++)
#pragma unroll
        for (int q = 0; q < 4; q++) acc[j][q] = 0.0f;

    // ldmatrix lane addressing: row = (lane&15), col-half = (lane>>4)*8
    uint32_t aAddr = smem_u32(Ash)
                   + ((uint32_t)(warp * 16 + (lane & 15)) * APAD + (lane >> 4) * 8) * 2;
    uint32_t bBase = smem_u32(Wsh)
                   + ((uint32_t)(lane & 15) * APAD + (lane >> 4) * 8) * 2;

#pragma unroll
    for (int k = 0; k < 8; k++) {
        uint32_t a0, a1, a2, a3;
        asm volatile(
            "ldmatrix.sync.aligned.m8n8.x4.shared.b16 {%0,%1,%2,%3}, [%4];"
            : "=r"(a0), "=r"(a1), "=r"(a2), "=r"(a3)
            : "r"(aAddr + (uint32_t)(k * 16 * 2)));
        uint32_t bRow = bBase + (uint32_t)(k * 16 * APAD * 2);
#pragma unroll
        for (int jg = 0; jg < 8; jg++) {
            uint32_t b0, b1, b2, b3;
            asm volatile(
                "ldmatrix.sync.aligned.m8n8.x4.trans.shared.b16 {%0,%1,%2,%3}, [%4];"
                : "=r"(b0), "=r"(b1), "=r"(b2), "=r"(b3)
                : "r"(bRow + (uint32_t)(jg * 16 * 2)));
            asm volatile(
                "mma.sync.aligned.m16n8k16.row.col.f32.f16.f16.f32 "
                "{%0,%1,%2,%3}, {%4,%5,%6,%7}, {%8,%9}, {%0,%1,%2,%3};"
                : "+f"(acc[2 * jg][0]), "+f"(acc[2 * jg][1]),
                  "+f"(acc[2 * jg][2]), "+f"(acc[2 * jg][3])
                : "r"(a0), "r"(a1), "r"(a2), "r"(a3), "r"(b0), "r"(b1));
            asm volatile(
                "mma.sync.aligned.m16n8k16.row.col.f32.f16.f16.f32 "
                "{%0,%1,%2,%3}, {%4,%5,%6,%7}, {%8,%9}, {%0,%1,%2,%3};"
                : "+f"(acc[2 * jg + 1][0]), "+f"(acc[2 * jg + 1][1]),
                  "+f"(acc[2 * jg + 1][2]), "+f"(acc[2 * jg + 1][3])
                : "r"(a0), "r"(a1), "r"(a2), "r"(a3), "r"(b2), "r"(b3));
        }
    }

    // Register epilogue. c0,c1 = (row g, cols 2t,2t+1); c2,c3 = (row g+8).
    int g = lane >> 2, t = lane & 3;
    int row_lo = row0 + warp * 16 + g;
    int row_hi = row_lo + 8;
    bool ok_lo = row_lo < n, ok_hi = row_hi < n;
    float ns_lo = 0.f, ns_hi = 0.f;
    if (mode == 1) {
        if (ok_lo) ns_lo = g_ns[row_lo];
        if (ok_hi) ns_hi = g_ns[row_hi];
    }
#pragma unroll
    for (int j = 0; j < 16; j++) {
        int cl = j * 8 + t * 2;
        float2 bb = __ldg((const float2*)(bias + cl));
        float v0 = acc[j][0] + bb.x, v1 = acc[j][1] + bb.y;   // row_lo
        float w0 = acc[j][2] + bb.x, w1 = acc[j][3] + bb.y;   // row_hi
        if (mode == 1) {
            v0 = fmaxf(v0, 0.f) * ns_lo; v1 = fmaxf(v1, 0.f) * ns_lo;
            w0 = fmaxf(w0, 0.f) * ns_hi; w1 = fmaxf(w1, 0.f) * ns_hi;
            if (ok_lo) *(__half2*)(g_hs + row_lo * D + cl) = __floats2half2_rn(v0, v1);
            if (ok_hi) *(__half2*)(g_hs + row_hi * D + cl) = __floats2half2_rn(w0, w1);
        } else {
            if (ok_lo) *(float2*)(out + row_lo * D + cl) = make_float2(v0, v1);
            if (ok_hi) *(float2*)(out + row_hi * D + cl) = make_float2(w0, w1);
        }
    }
}

// ---------------------------------------------------------------------------
extern "C" void kernel_launch(void* const* d_in, const int* in_sizes, int n_in,
                              void* d_out, int out_size) {
    const float* feat = (const float*)d_in[0];
    const float* W1   = (const float*)d_in[1];
    const float* b1   = (const float*)d_in[2];
    const float* W2   = (const float*)d_in[3];
    const float* b2   = (const float*)d_in[4];
    const int*   src  = (const int*)d_in[5];
    const int*   dst  = (const int*)d_in[6];
    float* out = (float*)d_out;

    int n_nodes = in_sizes[0] / D;
    int n_edges = in_sizes[5];
    if (n_nodes > MAX_NODES) n_nodes = MAX_NODES;

    cudaFuncSetAttribute(gemm_mma_kernel,
                         cudaFuncAttributeMaxDynamicSharedMemorySize,
                         GEMM_DYN_SMEM);

    // Zero degree/cursor arrays via async memset (graph-capturable, no kernel)
    void *degs_ptr = nullptr, *cnt_ptr = nullptr;
    cudaGetSymbolAddress(&degs_ptr, g_degs);
    cudaGetSymbolAddress(&cnt_ptr, g_cnt);
    cudaMemsetAsync(degs_ptr, 0, n_nodes * sizeof(int));
    cudaMemsetAsync(cnt_ptr, 0, n_nodes * sizeof(int));

    int node_blocks = (n_nodes * 32 + 255) / 256;
    int w_blocks = (2 * D * D + 255) / 256;          // 128
    int agg_blocks = ((n_nodes + 1) / 2 * 32 + 255) / 256;
    int gemm_blocks = (n_nodes + 127) / 128;
    int e4 = (n_edges + 3) / 4;

    edgefill_kernel<<<(e4 + 255) / 256, 256>>>((const int4*)src,
                                               (const int4*)dst, e4, n_edges);
    prep_kernel<<<node_blocks + w_blocks, 256>>>((const float4*)feat, W1, W2,
                                                 n_nodes, node_blocks);

    // Layer 1  (gemm is kernel #4 -> lands in the ncu capture slot)
    aggregate_kernel<<<agg_blocks, 256>>>(n_nodes);
    gemm_mma_kernel<<<gemm_blocks, 256, GEMM_DYN_SMEM>>>(0, b1, nullptr,
                                                         n_nodes, 1);

    // Layer 2
    aggregate_kernel<<<agg_blocks, 256>>>(n_nodes);
    gemm_mma_kernel<<<gemm_blocks, 256, GEMM_DYN_SMEM>>>(1, b2, out,
                                                         n_nodes, 0);
}

// round 16
// speedup vs baseline: 1.0959x; 1.0179x over previous
#include <cuda_runtime.h>
#include <cuda_fp16.h>
#include <cstdint>

#define MAX_NODES 50000
#define PAD_NODES 50176   // multiple of 128 (tile safety)
#define CSR_STRIDE 96
#define D 128
#define D4 (D / 4)

#define APAD 136                       // padded row: 272B (68 words ≡ 4 mod 32)
#define GEMM_DYN_SMEM (2 * 128 * APAD * 2)   // Ash + Wsh = 69632 B
#define GEMM_THREADS 512

// Scratch (device globals — no allocation allowed in kernel_launch)
__device__ __align__(256) __half g_hs[PAD_NODES * D];    // fp16 messages (ns applied)
__device__ __align__(256) __half g_aggh[PAD_NODES * D];  // fp16 agg result (*nd applied)
__device__ __align__(256) __half g_w16[2][D * D];        // fp16 weights [k][n]
__device__ float g_ns[MAX_NODES];                        // rsqrt(out_deg)
__device__ int   g_degs[MAX_NODES];                      // REAL out-degree (init 0)
__device__ int   g_cnt[MAX_NODES];                       // real in-degree / fill cursor
__device__ __align__(16) int g_csr[MAX_NODES * CSR_STRIDE]; // fixed-stride CSR (by dst)

static __device__ __forceinline__ uint32_t smem_u32(const void* p) {
    uint32_t a;
    asm("{ .reg .u64 t; cvta.to.shared.u64 t, %1; cvt.u32.u64 %0, t; }"
        : "=r"(a) : "l"(p));
    return a;
}

// ---------------------------------------------------------------------------
// K1: one pass over edges — out-degree count + CSR fill (cursor = in-degree).
__global__ void edgefill_kernel(const int4* __restrict__ src4,
                                const int4* __restrict__ dst4, int e4, int e) {
    int i = blockIdx.x * blockDim.x + threadIdx.x;
    if (i >= e4) return;
    int4 s = __ldg(src4 + i);
    int4 d = __ldg(dst4 + i);
    int rem = e - i * 4;
#define EF_ONE(SS, DD, K)                                              \
    if (K < rem) {                                                     \
        atomicAdd(&g_degs[SS], 1);                                     \
        int pos = atomicAdd(&g_cnt[DD], 1);                            \
        if (pos < CSR_STRIDE) g_csr[(DD) * CSR_STRIDE + pos] = (SS);   \
    }
    EF_ONE(s.x, d.x, 0)
    EF_ONE(s.y, d.y, 1)
    EF_ONE(s.z, d.z, 2)
    EF_ONE(s.w, d.w, 3)
#undef EF_ONE
}

// K2: node part: ns + hs = half(feat*ns). Tail blocks: W1/W2 -> fp16.
__global__ void prep_kernel(const float4* __restrict__ feat,
                            const float* __restrict__ W1,
                            const float* __restrict__ W2,
                            int n, int node_blocks) {
    if ((int)blockIdx.x >= node_blocks) {
        int i = (blockIdx.x - node_blocks) * 256 + threadIdx.x;  // 0..32767
        if (i < D * D)           g_w16[0][i]         = __float2half_rn(W1[i]);
        else if (i < 2 * D * D)  g_w16[1][i - D * D] = __float2half_rn(W2[i - D * D]);
        return;
    }
    int t = blockIdx.x * blockDim.x + threadIdx.x;
    int node = t >> 5;
    int part = t & 31;
    if (node >= n) return;
    float ns = rsqrtf((float)(g_degs[node] + 1));   // +1 = self loop
    if (part == 0) g_ns[node] = ns;
    float4 v = feat[node * D4 + part];
    __half2 h0 = __floats2half2_rn(v.x * ns, v.y * ns);
    __half2 h1 = __floats2half2_rn(v.z * ns, v.w * ns);
    uint2 u;
    u.x = *(unsigned*)&h0;
    u.y = *(unsigned*)&h1;
    ((uint2*)g_hs)[node * 32 + part] = u;
}

// ---------------------------------------------------------------------------
// K3/K5: CSR gather aggregation — R8's TREE4 form (regs 32, occ 94%); at its
// L2-traffic floor. Frozen.
#define ACC8(A, U) do {                                                 \
        float2 _f;                                                      \
        _f = __half22float2(*(__half2*)&(U).x); A[0] += _f.x; A[1] += _f.y; \
        _f = __half22float2(*(__half2*)&(U).y); A[2] += _f.x; A[3] += _f.y; \
        _f = __half22float2(*(__half2*)&(U).z); A[4] += _f.x; A[5] += _f.y; \
        _f = __half22float2(*(__half2*)&(U).w); A[6] += _f.x; A[7] += _f.y; \
    } while (0)

#define HADD2V4(R, X, Y) do {                                               \
        *(__half2*)&(R).x = __hadd2(*(__half2*)&(X).x, *(__half2*)&(Y).x);  \
        *(__half2*)&(R).y = __hadd2(*(__half2*)&(X).y, *(__half2*)&(Y).y);  \
        *(__half2*)&(R).z = __hadd2(*(__half2*)&(X).z, *(__half2*)&(Y).z);  \
        *(__half2*)&(R).w = __hadd2(*(__half2*)&(X).w, *(__half2*)&(Y).w);  \
    } while (0)

#define TREE4(A, E0, E1, E2, E3) do {                                   \
        uint4 _u0 = __ldg(hsv + (E0) * 16 + hl);                        \
        uint4 _u1 = __ldg(hsv + (E1) * 16 + hl);                        \
        uint4 _u2 = __ldg(hsv + (E2) * 16 + hl);                        \
        uint4 _u3 = __ldg(hsv + (E3) * 16 + hl);                        \
        uint4 _s01, _s23, _s;                                           \
        HADD2V4(_s01, _u0, _u1);                                        \
        HADD2V4(_s23, _u2, _u3);                                        \
        HADD2V4(_s, _s01, _s23);                                        \
        ACC8(A, _s);                                                    \
    } while (0)

__global__ void __launch_bounds__(256) aggregate_kernel(int n) {
    int gw   = (blockIdx.x * blockDim.x + threadIdx.x) >> 5;
    int lane = threadIdx.x & 31;
    int half = lane >> 4;
    int hl   = lane & 15;
    int node = gw * 2 + half;
    if (gw * 2 >= n) return;
    if (node >= n) node = n - 1;

    const uint4* hsv = (const uint4*)g_hs;

    float a[8];
    {   // self-loop seed
        uint4 s = __ldg(hsv + node * 16 + hl);
        a[0] = a[1] = a[2] = a[3] = a[4] = a[5] = a[6] = a[7] = 0.f;
        ACC8(a, s);
    }

    int cnt = g_cnt[node];
    int ce  = cnt < CSR_STRIDE ? cnt : CSR_STRIDE;
    const int* row = g_csr + node * CSR_STRIDE;

    int base = 0;
    for (; base + 8 <= ce; base += 8) {
        int4 e0 = __ldg((const int4*)(row + base));
        int4 e1 = __ldg((const int4*)(row + base + 4));
        TREE4(a, e0.x, e0.y, e0.z, e0.w);
        TREE4(a, e1.x, e1.y, e1.z, e1.w);
    }
    if (base + 4 <= ce) {
        int4 e0 = __ldg((const int4*)(row + base));
        TREE4(a, e0.x, e0.y, e0.z, e0.w);
        base += 4;
    }
    for (; base < ce; base++) {
        int ei = __ldg(row + base);
        uint4 u = __ldg(hsv + ei * 16 + hl);
        ACC8(a, u);
    }

    float nd = rsqrtf((float)(cnt + 1));
    __half2 h0 = __floats2half2_rn(a[0] * nd, a[1] * nd);
    __half2 h1 = __floats2half2_rn(a[2] * nd, a[3] * nd);
    __half2 h2 = __floats2half2_rn(a[4] * nd, a[5] * nd);
    __half2 h3 = __floats2half2_rn(a[6] * nd, a[7] * nd);
    uint4 o;
    o.x = *(unsigned*)&h0; o.y = *(unsigned*)&h1;
    o.z = *(unsigned*)&h2; o.w = *(unsigned*)&h3;
    ((uint4*)g_aggh)[node * 16 + hl] = o;
}

// ---------------------------------------------------------------------------
// K4/K6: explicit mma.sync GEMM. 512 threads, warp tile = 16 rows x 64 cols
// (rg = warp>>1, cg = warp&1): 32 acc regs/warp, 5 LDSM + 8 MMA per k-step,
// 2 CTAs/SM = 32 warps/SM. Register epilogue, no smem band.
__global__ void __launch_bounds__(GEMM_THREADS, 2)
gemm_mma_kernel(int layer, const float* __restrict__ bias,
                float* __restrict__ out, int n, int mode) {
    extern __shared__ unsigned char dyn[];
    __half* Ash = (__half*)dyn;                 // 128 x APAD
    __half* Wsh = Ash + 128 * APAD;             // 128 x APAD

    int tid = threadIdx.x, warp = tid >> 5, lane = tid & 31;
    int rg = warp >> 1;       // row group 0..7  -> rows [rg*16, rg*16+16)
    int cg = warp & 1;        // col group 0..1  -> cols [cg*64, cg*64+64)
    int row0 = blockIdx.x * 128;

    // Cooperative coalesced staging (A rows < PAD_NODES always).
    const uint4* Ag = (const uint4*)(g_aggh + (size_t)row0 * D);
    const uint4* Wg = (const uint4*)g_w16[layer];
#pragma unroll
    for (int s = 0; s < 4; s++) {
        int i = tid + GEMM_THREADS * s;     // 0..2047
        int r = i >> 4, c = i & 15;
        ((uint4*)Ash)[r * (APAD / 8) + c] = Ag[i];
        ((uint4*)Wsh)[r * (APAD / 8) + c] = Wg[i];
    }
    __syncthreads();

    float acc[8][4];
#pragma unroll
    for (int j = 0; j < 8; j++)
#pragma unroll
        for (int q = 0; q < 4; q++) acc[j][q] = 0.0f;

    // ldmatrix lane addressing: row = (lane&15), col-half = (lane>>4)*8
    uint32_t aAddr = smem_u32(Ash)
                   + ((uint32_t)(rg * 16 + (lane & 15)) * APAD + (lane >> 4) * 8) * 2;
    uint32_t bBase = smem_u32(Wsh)
                   + ((uint32_t)(lane & 15) * APAD + cg * 64 + (lane >> 4) * 8) * 2;

#pragma unroll
    for (int k = 0; k < 8; k++) {
        uint32_t a0, a1, a2, a3;
        asm volatile(
            "ldmatrix.sync.aligned.m8n8.x4.shared.b16 {%0,%1,%2,%3}, [%4];"
            : "=r"(a0), "=r"(a1), "=r"(a2), "=r"(a3)
            : "r"(aAddr + (uint32_t)(k * 16 * 2)));
        uint32_t bRow = bBase + (uint32_t)(k * 16 * APAD * 2);
#pragma unroll
        for (int jg = 0; jg < 4; jg++) {
            uint32_t b0, b1, b2, b3;
            asm volatile(
                "ldmatrix.sync.aligned.m8n8.x4.trans.shared.b16 {%0,%1,%2,%3}, [%4];"
                : "=r"(b0), "=r"(b1), "=r"(b2), "=r"(b3)
                : "r"(bRow + (uint32_t)(jg * 16 * 2)));
            asm volatile(
                "mma.sync.aligned.m16n8k16.row.col.f32.f16.f16.f32 "
                "{%0,%1,%2,%3}, {%4,%5,%6,%7}, {%8,%9}, {%0,%1,%2,%3};"
                : "+f"(acc[2 * jg][0]), "+f"(acc[2 * jg][1]),
                  "+f"(acc[2 * jg][2]), "+f"(acc[2 * jg][3])
                : "r"(a0), "r"(a1), "r"(a2), "r"(a3), "r"(b0), "r"(b1));
            asm volatile(
                "mma.sync.aligned.m16n8k16.row.col.f32.f16.f16.f32 "
                "{%0,%1,%2,%3}, {%4,%5,%6,%7}, {%8,%9}, {%0,%1,%2,%3};"
                : "+f"(acc[2 * jg + 1][0]), "+f"(acc[2 * jg + 1][1]),
                  "+f"(acc[2 * jg + 1][2]), "+f"(acc[2 * jg + 1][3])
                : "r"(a0), "r"(a1), "r"(a2), "r"(a3), "r"(b2), "r"(b3));
        }
    }

    // Register epilogue. c0,c1 = (row g, cols 2t,2t+1); c2,c3 = (row g+8).
    int g = lane >> 2, t = lane & 3;
    int row_lo = row0 + rg * 16 + g;
    int row_hi = row_lo + 8;
    bool ok_lo = row_lo < n, ok_hi = row_hi < n;
    float ns_lo = 0.f, ns_hi = 0.f;
    if (mode == 1) {
        if (ok_lo) ns_lo = g_ns[row_lo];
        if (ok_hi) ns_hi = g_ns[row_hi];
    }
#pragma unroll
    for (int j = 0; j < 8; j++) {
        int cl = cg * 64 + j * 8 + t * 2;
        float2 bb = __ldg((const float2*)(bias + cl));
        float v0 = acc[j][0] + bb.x, v1 = acc[j][1] + bb.y;   // row_lo
        float w0 = acc[j][2] + bb.x, w1 = acc[j][3] + bb.y;   // row_hi
        if (mode == 1) {
            v0 = fmaxf(v0, 0.f) * ns_lo; v1 = fmaxf(v1, 0.f) * ns_lo;
            w0 = fmaxf(w0, 0.f) * ns_hi; w1 = fmaxf(w1, 0.f) * ns_hi;
            if (ok_lo) *(__half2*)(g_hs + row_lo * D + cl) = __floats2half2_rn(v0, v1);
            if (ok_hi) *(__half2*)(g_hs + row_hi * D + cl) = __floats2half2_rn(w0, w1);
        } else {
            if (ok_lo) *(float2*)(out + row_lo * D + cl) = make_float2(v0, v1);
            if (ok_hi) *(float2*)(out + row_hi * D + cl) = make_float2(w0, w1);
        }
    }
}

// ---------------------------------------------------------------------------
extern "C" void kernel_launch(void* const* d_in, const int* in_sizes, int n_in,
                              void* d_out, int out_size) {
    const float* feat = (const float*)d_in[0];
    const float* W1   = (const float*)d_in[1];
    const float* b1   = (const float*)d_in[2];
    const float* W2   = (const float*)d_in[3];
    const float* b2   = (const float*)d_in[4];
    const int*   src  = (const int*)d_in[5];
    const int*   dst  = (const int*)d_in[6];
    float* out = (float*)d_out;

    int n_nodes = in_sizes[0] / D;
    int n_edges = in_sizes[5];
    if (n_nodes > MAX_NODES) n_nodes = MAX_NODES;

    cudaFuncSetAttribute(gemm_mma_kernel,
                         cudaFuncAttributeMaxDynamicSharedMemorySize,
                         GEMM_DYN_SMEM);

    // Zero degree/cursor arrays via async memset (graph-capturable, no kernel)
    void *degs_ptr = nullptr, *cnt_ptr = nullptr;
    cudaGetSymbolAddress(&degs_ptr, g_degs);
    cudaGetSymbolAddress(&cnt_ptr, g_cnt);
    cudaMemsetAsync(degs_ptr, 0, n_nodes * sizeof(int));
    cudaMemsetAsync(cnt_ptr, 0, n_nodes * sizeof(int));

    int node_blocks = (n_nodes * 32 + 255) / 256;
    int w_blocks = (2 * D * D + 255) / 256;          // 128
    int agg_blocks = ((n_nodes + 1) / 2 * 32 + 255) / 256;
    int gemm_blocks = (n_nodes + 127) / 128;
    int e4 = (n_edges + 3) / 4;

    edgefill_kernel<<<(e4 + 255) / 256, 256>>>((const int4*)src,
                                               (const int4*)dst, e4, n_edges);
    prep_kernel<<<node_blocks + w_blocks, 256>>>((const float4*)feat, W1, W2,
                                                 n_nodes, node_blocks);

    // Layer 1  (gemm is kernel #4 -> lands in the ncu capture slot)
    aggregate_kernel<<<agg_blocks, 256>>>(n_nodes);
    gemm_mma_kernel<<<gemm_blocks, GEMM_THREADS, GEMM_DYN_SMEM>>>(0, b1,
                                                                  nullptr,
                                                                  n_nodes, 1);

    // Layer 2
    aggregate_kernel<<<agg_blocks, 256>>>(n_nodes);
    gemm_mma_kernel<<<gemm_blocks, GEMM_THREADS, GEMM_DYN_SMEM>>>(1, b2, out,
                                                                  n_nodes, 0);
}